// round 14
// baseline (speedup 1.0000x reference)
#include <cuda_runtime.h>
#include <cuda_bf16.h>

#define NTHREADS 256
#define NBLOCKS 6250   // 6250*256 = 1.6M threads; 8M boxes -> exactly 5 iters/thread

// Global accumulators; statically zero. Last block resets them after use ->
// graph-replay safe. No init kernel, no per-block partial arrays.
__device__ double g_iou_d = 0.0;
__device__ double g_mse_d = 0.0;
__device__ unsigned long long g_ni_u = 0ull;
__device__ unsigned int g_ticket = 0u;

__global__ void __launch_bounds__(NTHREADS) iou_dots_fused(
    const float4* __restrict__ pr,
    const float4* __restrict__ gt,
    float* __restrict__ out,
    int n)
{
    float iou_sum = 0.0f;
    float mse_sum = 0.0f;
    unsigned int n_inc = 0u;

    // Simple branchy grid-stride loop (empirically the fastest body).
    const int stride = gridDim.x * blockDim.x;
    for (int i = blockIdx.x * blockDim.x + threadIdx.x; i < n; i += stride) {
        const float4 p = pr[i];
        const float4 g = gt[i];

        const float x_min_t = g.x - g.z * 0.5f;
        const float x_max_t = g.x + g.z * 0.5f;
        const float y_min_t = g.y - g.w * 0.5f;
        const float y_max_t = g.y + g.w * 0.5f;
        const float x_min_p = fmaxf(p.x - p.z * 0.5f, 0.0f);
        const float x_max_p = fminf(p.x + p.z * 0.5f, 1.0f);
        const float y_min_p = fmaxf(p.y - p.w * 0.5f, 0.0f);
        const float y_max_p = fminf(p.y + p.w * 0.5f, 1.0f);
        const float o0 = fmaxf(x_min_t, x_min_p);
        const float o1 = fmaxf(y_min_t, y_min_p);
        const float o2 = fminf(x_max_t, x_max_p);
        const float o3 = fminf(y_max_t, y_max_p);

        const bool incorrect = (o2 < o0) || (o3 < o1);
        if (incorrect) {
            n_inc++;
            const float dx = p.x - g.x;
            const float dy = p.y - g.y;
            const float dz = p.z - g.z;
            const float dw = p.w - g.w;
            mse_sum += dx * dx + dy * dy + dz * dz + dw * dw;
        } else {
            const float inter = (o2 - o0) * (o3 - o1);
            const float area_p = p.z * p.w;
            const float area_g = g.z * g.w;
            iou_sum += inter / (area_p + area_g - inter + 1e-7f);
        }
    }

    // intra-warp reduce
    #pragma unroll
    for (int off = 16; off > 0; off >>= 1) {
        iou_sum += __shfl_down_sync(0xFFFFFFFFu, iou_sum, off);
        mse_sum += __shfl_down_sync(0xFFFFFFFFu, mse_sum, off);
        n_inc   += __shfl_down_sync(0xFFFFFFFFu, n_inc, off);
    }

    __shared__ float s_iou[8];
    __shared__ float s_mse[8];
    __shared__ unsigned int s_ni[8];
    __shared__ bool s_last;
    const int wid = threadIdx.x >> 5;
    const int lid = threadIdx.x & 31;
    if (lid == 0) {
        s_iou[wid] = iou_sum;
        s_mse[wid] = mse_sum;
        s_ni[wid] = n_inc;
    }
    __syncthreads();
    if (threadIdx.x == 0) {
        float biou = 0.0f, bmse = 0.0f;
        unsigned int bni = 0u;
        #pragma unroll
        for (int w = 0; w < NTHREADS / 32; w++) {
            biou += s_iou[w];
            bmse += s_mse[w];
            bni += s_ni[w];
        }
        // Direct global atomics: cheapest possible tail.
        atomicAdd(&g_iou_d, (double)biou);
        atomicAdd(&g_mse_d, (double)bmse);
        atomicAdd(&g_ni_u, (unsigned long long)bni);
        __threadfence();
        const unsigned int old = atomicAdd(&g_ticket, 1u);
        s_last = (old == gridDim.x - 1u);
    }
    __syncthreads();

    if (s_last && threadIdx.x == 0) {
        __threadfence();
        const double tiou = g_iou_d;
        const double tmse = g_mse_d;
        const unsigned long long tni = g_ni_u;
        const unsigned long long tnc = (unsigned long long)n - tni;
        const double mse_denom = (double)((tni > 0ull) ? tni * 4ull : 1ull);
        const double iou_denom = (double)((tnc > 0ull) ? tnc : 1ull);
        const float mse_mean = (float)(tmse / mse_denom);
        const float iou_mean = (float)(tiou / iou_denom);
        const float res_full = iou_mean + ((tni > 0ull) ? -mse_mean : 0.0f);
        out[0] = (tnc > 0ull) ? res_full : -mse_mean;
        // Reset accumulators for the next graph replay.
        g_iou_d = 0.0;
        g_mse_d = 0.0;
        g_ni_u = 0ull;
        g_ticket = 0u;
    }
}

extern "C" void kernel_launch(void* const* d_in, const int* in_sizes, int n_in,
                              void* d_out, int out_size) {
    const float4* pr = (const float4*)d_in[0];
    const float4* gt = (const float4*)d_in[1];
    float* out = (float*)d_out;
    const int n = in_sizes[0] / 4;

    iou_dots_fused<<<NBLOCKS, NTHREADS>>>(pr, gt, out, n);
}

// round 15
// speedup vs baseline: 1.1915x; 1.1915x over previous
#include <cuda_runtime.h>
#include <cuda_bf16.h>

#define NTHREADS 256
#define NBLOCKS 2368   // empirically best: 2 full waves @ 8 CTAs/SM

// Global accumulators; statically zero. Last block resets them after use ->
// graph-replay safe. No init kernel, no per-block partial arrays.
__device__ double g_iou_d = 0.0;
__device__ double g_mse_d = 0.0;
__device__ unsigned long long g_ni_u = 0ull;
__device__ unsigned int g_ticket = 0u;

__global__ void __launch_bounds__(NTHREADS) iou_dots_fused(
    const float4* __restrict__ pr,
    const float4* __restrict__ gt,
    float* __restrict__ out,
    int n)
{
    float iou_sum = 0.0f;
    float mse_sum = 0.0f;
    unsigned int n_inc = 0u;

    // Branchy grid-stride loop (empirically fastest body), streaming loads.
    const int stride = gridDim.x * blockDim.x;
    for (int i = blockIdx.x * blockDim.x + threadIdx.x; i < n; i += stride) {
        const float4 p = __ldcs(pr + i);
        const float4 g = __ldcs(gt + i);

        const float x_min_t = g.x - g.z * 0.5f;
        const float x_max_t = g.x + g.z * 0.5f;
        const float y_min_t = g.y - g.w * 0.5f;
        const float y_max_t = g.y + g.w * 0.5f;
        const float x_min_p = fmaxf(p.x - p.z * 0.5f, 0.0f);
        const float x_max_p = fminf(p.x + p.z * 0.5f, 1.0f);
        const float y_min_p = fmaxf(p.y - p.w * 0.5f, 0.0f);
        const float y_max_p = fminf(p.y + p.w * 0.5f, 1.0f);
        const float o0 = fmaxf(x_min_t, x_min_p);
        const float o1 = fmaxf(y_min_t, y_min_p);
        const float o2 = fminf(x_max_t, x_max_p);
        const float o3 = fminf(y_max_t, y_max_p);

        const bool incorrect = (o2 < o0) || (o3 < o1);
        if (incorrect) {
            n_inc++;
            const float dx = p.x - g.x;
            const float dy = p.y - g.y;
            const float dz = p.z - g.z;
            const float dw = p.w - g.w;
            mse_sum += dx * dx + dy * dy + dz * dz + dw * dw;
        } else {
            const float inter = (o2 - o0) * (o3 - o1);
            const float area_p = p.z * p.w;
            const float area_g = g.z * g.w;
            iou_sum += inter / (area_p + area_g - inter + 1e-7f);
        }
    }

    // intra-warp reduce
    #pragma unroll
    for (int off = 16; off > 0; off >>= 1) {
        iou_sum += __shfl_down_sync(0xFFFFFFFFu, iou_sum, off);
        mse_sum += __shfl_down_sync(0xFFFFFFFFu, mse_sum, off);
        n_inc   += __shfl_down_sync(0xFFFFFFFFu, n_inc, off);
    }

    __shared__ float s_iou[8];
    __shared__ float s_mse[8];
    __shared__ unsigned int s_ni[8];
    __shared__ bool s_last;
    const int wid = threadIdx.x >> 5;
    const int lid = threadIdx.x & 31;
    if (lid == 0) {
        s_iou[wid] = iou_sum;
        s_mse[wid] = mse_sum;
        s_ni[wid] = n_inc;
    }
    __syncthreads();
    if (threadIdx.x == 0) {
        float biou = 0.0f, bmse = 0.0f;
        unsigned int bni = 0u;
        #pragma unroll
        for (int w = 0; w < NTHREADS / 32; w++) {
            biou += s_iou[w];
            bmse += s_mse[w];
            bni += s_ni[w];
        }
        // Direct global atomics: cheapest possible tail.
        atomicAdd(&g_iou_d, (double)biou);
        atomicAdd(&g_mse_d, (double)bmse);
        atomicAdd(&g_ni_u, (unsigned long long)bni);
        __threadfence();
        const unsigned int old = atomicAdd(&g_ticket, 1u);
        s_last = (old == gridDim.x - 1u);
    }
    __syncthreads();

    if (s_last && threadIdx.x == 0) {
        __threadfence();
        const double tiou = g_iou_d;
        const double tmse = g_mse_d;
        const unsigned long long tni = g_ni_u;
        const unsigned long long tnc = (unsigned long long)n - tni;
        const double mse_denom = (double)((tni > 0ull) ? tni * 4ull : 1ull);
        const double iou_denom = (double)((tnc > 0ull) ? tnc : 1ull);
        const float mse_mean = (float)(tmse / mse_denom);
        const float iou_mean = (float)(tiou / iou_denom);
        const float res_full = iou_mean + ((tni > 0ull) ? -mse_mean : 0.0f);
        out[0] = (tnc > 0ull) ? res_full : -mse_mean;
        // Reset accumulators for the next graph replay.
        g_iou_d = 0.0;
        g_mse_d = 0.0;
        g_ni_u = 0ull;
        g_ticket = 0u;
    }
}

extern "C" void kernel_launch(void* const* d_in, const int* in_sizes, int n_in,
                              void* d_out, int out_size) {
    const float4* pr = (const float4*)d_in[0];
    const float4* gt = (const float4*)d_in[1];
    float* out = (float*)d_out;
    const int n = in_sizes[0] / 4;

    iou_dots_fused<<<NBLOCKS, NTHREADS>>>(pr, gt, out, n);
}

// round 16
// speedup vs baseline: 1.2281x; 1.0307x over previous
#include <cuda_runtime.h>
#include <cuda_bf16.h>

#define NTHREADS 256
#define NBLOCKS 2368   // empirically best: fine-grained, ~2.3 waves

// Global accumulators; statically zero. Last block resets them after use ->
// graph-replay safe. No init kernel, no per-block partial arrays.
__device__ double g_iou_d = 0.0;
__device__ double g_mse_d = 0.0;
__device__ unsigned long long g_ni_u = 0ull;
__device__ unsigned int g_ticket = 0u;

__device__ __forceinline__ void process_box(const float4 p, const float4 g,
                                            float& iou_sum, float& mse_sum,
                                            unsigned int& n_inc) {
    const float x_min_t = g.x - g.z * 0.5f;
    const float x_max_t = g.x + g.z * 0.5f;
    const float y_min_t = g.y - g.w * 0.5f;
    const float y_max_t = g.y + g.w * 0.5f;
    const float x_min_p = fmaxf(p.x - p.z * 0.5f, 0.0f);
    const float x_max_p = fminf(p.x + p.z * 0.5f, 1.0f);
    const float y_min_p = fmaxf(p.y - p.w * 0.5f, 0.0f);
    const float y_max_p = fminf(p.y + p.w * 0.5f, 1.0f);
    const float o0 = fmaxf(x_min_t, x_min_p);
    const float o1 = fmaxf(y_min_t, y_min_p);
    const float o2 = fminf(x_max_t, x_max_p);
    const float o3 = fminf(y_max_t, y_max_p);

    const bool incorrect = (o2 < o0) || (o3 < o1);
    if (incorrect) {
        n_inc++;
        const float dx = p.x - g.x;
        const float dy = p.y - g.y;
        const float dz = p.z - g.z;
        const float dw = p.w - g.w;
        mse_sum += dx * dx + dy * dy + dz * dz + dw * dw;
    } else {
        const float inter = (o2 - o0) * (o3 - o1);
        const float area_p = p.z * p.w;
        const float area_g = g.z * g.w;
        iou_sum += inter / (area_p + area_g - inter + 1e-7f);
    }
}

__global__ void __launch_bounds__(NTHREADS) iou_dots_fused(
    const float4* __restrict__ pr,
    const float4* __restrict__ gt,
    float* __restrict__ out,
    int n)
{
    float iou_sum = 0.0f;
    float mse_sum = 0.0f;
    unsigned int n_inc = 0u;

    const int stride = gridDim.x * blockDim.x;
    int i = blockIdx.x * blockDim.x + threadIdx.x;

    // x2 unroll: 4 streaming LDG.128 front-batched before any compute.
    for (; i + stride < n; i += 2 * stride) {
        const float4 p0 = __ldcs(pr + i);
        const float4 g0 = __ldcs(gt + i);
        const float4 p1 = __ldcs(pr + i + stride);
        const float4 g1 = __ldcs(gt + i + stride);
        process_box(p0, g0, iou_sum, mse_sum, n_inc);
        process_box(p1, g1, iou_sum, mse_sum, n_inc);
    }
    if (i < n) {
        process_box(__ldcs(pr + i), __ldcs(gt + i), iou_sum, mse_sum, n_inc);
    }

    // intra-warp reduce
    #pragma unroll
    for (int off = 16; off > 0; off >>= 1) {
        iou_sum += __shfl_down_sync(0xFFFFFFFFu, iou_sum, off);
        mse_sum += __shfl_down_sync(0xFFFFFFFFu, mse_sum, off);
        n_inc   += __shfl_down_sync(0xFFFFFFFFu, n_inc, off);
    }

    __shared__ float s_iou[8];
    __shared__ float s_mse[8];
    __shared__ unsigned int s_ni[8];
    __shared__ bool s_last;
    const int wid = threadIdx.x >> 5;
    const int lid = threadIdx.x & 31;
    if (lid == 0) {
        s_iou[wid] = iou_sum;
        s_mse[wid] = mse_sum;
        s_ni[wid] = n_inc;
    }
    __syncthreads();
    if (threadIdx.x == 0) {
        float biou = 0.0f, bmse = 0.0f;
        unsigned int bni = 0u;
        #pragma unroll
        for (int w = 0; w < NTHREADS / 32; w++) {
            biou += s_iou[w];
            bmse += s_mse[w];
            bni += s_ni[w];
        }
        // Direct global atomics: cheapest possible tail.
        atomicAdd(&g_iou_d, (double)biou);
        atomicAdd(&g_mse_d, (double)bmse);
        atomicAdd(&g_ni_u, (unsigned long long)bni);
        __threadfence();
        const unsigned int old = atomicAdd(&g_ticket, 1u);
        s_last = (old == gridDim.x - 1u);
    }
    __syncthreads();

    if (s_last && threadIdx.x == 0) {
        __threadfence();
        const double tiou = g_iou_d;
        const double tmse = g_mse_d;
        const unsigned long long tni = g_ni_u;
        const unsigned long long tnc = (unsigned long long)n - tni;
        const double mse_denom = (double)((tni > 0ull) ? tni * 4ull : 1ull);
        const double iou_denom = (double)((tnc > 0ull) ? tnc : 1ull);
        const float mse_mean = (float)(tmse / mse_denom);
        const float iou_mean = (float)(tiou / iou_denom);
        const float res_full = iou_mean + ((tni > 0ull) ? -mse_mean : 0.0f);
        out[0] = (tnc > 0ull) ? res_full : -mse_mean;
        // Reset accumulators for the next graph replay.
        g_iou_d = 0.0;
        g_mse_d = 0.0;
        g_ni_u = 0ull;
        g_ticket = 0u;
    }
}

extern "C" void kernel_launch(void* const* d_in, const int* in_sizes, int n_in,
                              void* d_out, int out_size) {
    const float4* pr = (const float4*)d_in[0];
    const float4* gt = (const float4*)d_in[1];
    float* out = (float*)d_out;
    const int n = in_sizes[0] / 4;

    iou_dots_fused<<<NBLOCKS, NTHREADS>>>(pr, gt, out, n);
}